// round 16
// baseline (speedup 1.0000x reference)
#include <cuda_runtime.h>
#include <cuda_fp16.h>
#include <cstdint>

#define M_TOT 8192
#define D_DIM 2048
#define O_DIM 2048
#define E_NUM 8
#define R_DIM 16
#define KLORA 128
#define K_TOT 2176          // D_DIM + KLORA

// ---------------- scratch (fp16 stored as ushort) ----------------
__device__ float g_rw[M_TOT * E_NUM];
__device__ unsigned short g_Ah[(size_t)M_TOT * K_TOT];   // [X|Z] fp16
__device__ unsigned short g_Bh[(size_t)O_DIM * K_TOT];   // [W|Bcat] fp16
__device__ unsigned short g_Ach[(size_t)KLORA * D_DIM];  // Acat^T fp16

// ---------------- helpers ----------------
__device__ __forceinline__ uint32_t s2u(const void* p) {
    uint32_t a;
    asm("{ .reg .u64 t; cvta.to.shared.u64 t, %1; cvt.u32.u64 %0, t; }"
        : "=r"(a) : "l"(p));
    return a;
}
__device__ __forceinline__ void cp16(uint32_t dst, const void* src) {
    asm volatile("cp.async.cg.shared.global [%0], [%1], 16;" :: "r"(dst), "l"(src));
}
#define CP_COMMIT() asm volatile("cp.async.commit_group;" ::: "memory")
#define CP_WAIT1()  asm volatile("cp.async.wait_group 1;" ::: "memory")

__device__ __forceinline__ void ldm_x4(uint32_t* r, uint32_t addr) {
    asm volatile("ldmatrix.sync.aligned.m8n8.x4.shared.b16 {%0,%1,%2,%3}, [%4];"
        : "=r"(r[0]), "=r"(r[1]), "=r"(r[2]), "=r"(r[3]) : "r"(addr));
}
__device__ __forceinline__ void mma_fp16(float* d, const uint32_t* a,
                                         uint32_t b0, uint32_t b1) {
    asm volatile(
        "mma.sync.aligned.m16n8k16.row.col.f32.f16.f16.f32 "
        "{%0,%1,%2,%3}, {%4,%5,%6,%7}, {%8,%9}, {%0,%1,%2,%3};"
        : "+f"(d[0]), "+f"(d[1]), "+f"(d[2]), "+f"(d[3])
        : "r"(a[0]), "r"(a[1]), "r"(a[2]), "r"(a[3]), "r"(b0), "r"(b1));
}
__device__ __forceinline__ unsigned short hp(float v) {
    return __half_as_ushort(__float2half_rn(v));
}

// swizzled byte offset within a tile: row, 16B-chunk byte offset (0..127)
__device__ __forceinline__ uint32_t tswz(int row, int cbyte) {
    return (uint32_t)(row * 128 + (cbyte ^ ((row & 7) << 4)));
}

// ---------------------------------------------------------------------------
// Prep 1 (warp-parallel): x -> fp16 into cols [0,2048);
// router top-2 softmax -> g_rw. 32 rows per block, 4 rows per warp.
// ---------------------------------------------------------------------------
__global__ __launch_bounds__(256) void prep_rs_kernel(
    const float* __restrict__ x, const float* __restrict__ Wr)
{
    extern __shared__ float wr_s[];   // 16384 floats = 64KB
    const int tid = threadIdx.x;
    const int lane = tid & 31, warp = tid >> 5;

    for (int i = tid; i < 4096; i += 256)
        reinterpret_cast<float4*>(wr_s)[i] = reinterpret_cast<const float4*>(Wr)[i];
    __syncthreads();
    const float4* wr4 = reinterpret_cast<const float4*>(wr_s);

    const int m0 = blockIdx.x * 32;
#pragma unroll
    for (int r = 0; r < 4; r++) {
        const int m = m0 + warp * 4 + r;
        const float4* xr = reinterpret_cast<const float4*>(x + (size_t)m * D_DIM);
        float acc[E_NUM];
#pragma unroll
        for (int e = 0; e < E_NUM; e++) acc[e] = 0.f;

#pragma unroll 4
        for (int i = lane; i < D_DIM / 4; i += 32) {
            float4 xv = xr[i];
            ushort4 hv;
            hv.x = hp(xv.x); hv.y = hp(xv.y);
            hv.z = hp(xv.z); hv.w = hp(xv.w);
            *reinterpret_cast<ushort4*>(g_Ah + (size_t)m * K_TOT + i * 4) = hv;
#pragma unroll
            for (int e = 0; e < E_NUM; e++) {
                float4 wv = wr4[e * 512 + i];
                acc[e] += xv.x * wv.x + xv.y * wv.y + xv.z * wv.z + xv.w * wv.w;
            }
        }
#pragma unroll
        for (int e = 0; e < E_NUM; e++) {
#pragma unroll
            for (int off = 16; off > 0; off >>= 1)
                acc[e] += __shfl_xor_sync(0xffffffffu, acc[e], off);
        }
        if (lane == 0) {
            int i1 = 0;
#pragma unroll
            for (int e = 1; e < E_NUM; e++) if (acc[e] > acc[i1]) i1 = e;
            int i2 = -1;
#pragma unroll
            for (int e = 0; e < E_NUM; e++) {
                if (e == i1) continue;
                if (i2 < 0 || acc[e] > acc[i2]) i2 = e;
            }
            float e2 = __expf(acc[i2] - acc[i1]);
            float inv = 1.0f / (1.0f + e2);
            float out[E_NUM];
#pragma unroll
            for (int e = 0; e < E_NUM; e++) out[e] = 0.f;
            out[i1] = inv;
            out[i2] = e2 * inv;
            float4* dst = reinterpret_cast<float4*>(g_rw + (size_t)m * E_NUM);
            dst[0] = make_float4(out[0], out[1], out[2], out[3]);
            dst[1] = make_float4(out[4], out[5], out[6], out[7]);
        }
    }
}

// ---------------------------------------------------------------------------
// Prep 2: W -> g_Bh cols [0,2048); Bexp -> cols [2048,2176).
// ---------------------------------------------------------------------------
__global__ __launch_bounds__(256) void split_wb_kernel(
    const float* __restrict__ W, const float* __restrict__ Bexp)
{
    const int o = blockIdx.x;
    const int tid = threadIdx.x;
    const float4* src = reinterpret_cast<const float4*>(W + (size_t)o * D_DIM);
    for (int i = tid; i < D_DIM / 4; i += 256) {
        float4 v = src[i];
        ushort4 hv;
        hv.x = hp(v.x); hv.y = hp(v.y); hv.z = hp(v.z); hv.w = hp(v.w);
        *reinterpret_cast<ushort4*>(g_Bh + (size_t)o * K_TOT + i * 4) = hv;
    }
    if (tid < KLORA)
        g_Bh[(size_t)o * K_TOT + D_DIM + tid] = hp(Bexp[(size_t)tid * O_DIM + o]);
}

// ---------------------------------------------------------------------------
// Prep 3: Acat^T fp16: g_Ach[n][k], n = e*16+r.
// ---------------------------------------------------------------------------
__global__ __launch_bounds__(256) void split_acat_kernel(const float* __restrict__ A)
{
    const int n = blockIdx.x;
    const int e = n >> 4, r = n & 15;
    const int tid = threadIdx.x;
    for (int k = tid; k < D_DIM; k += 256)
        g_Ach[(size_t)n * D_DIM + k] =
            hp(A[(size_t)e * D_DIM * R_DIM + (size_t)k * R_DIM + r]);
}

// ---------------------------------------------------------------------------
// zgemm (fp16 single-pass): Z = (X @ Acat) * rw -> fp16, cols [2048,2176).
// Tile 64(M) x 128(N), BK=64, 3 stages. Stage = A 8K | B 16K = 24KB.
// 8 warps: wm = warp&1, wn = warp>>1; warp tile 32x32.
// ---------------------------------------------------------------------------
#define ZSTG 24576
#define ZSMEM (3 * ZSTG)

__global__ void __launch_bounds__(256, 1) zgemm_mma_kernel()
{
    extern __shared__ __align__(128) char smem[];
    const uint32_t sb = s2u(smem);
    const int tid = threadIdx.x;
    const int lane = tid & 31, warp = tid >> 5;
    const int wm = warp & 1, wn = warp >> 1;
    const int m0 = blockIdx.x * 64;

    float acc[2][4][4];
#pragma unroll
    for (int i = 0; i < 2; i++)
#pragma unroll
        for (int j = 0; j < 4; j++)
#pragma unroll
            for (int k = 0; k < 4; k++) acc[i][j][k] = 0.f;

    const int NT = 32;   // 2048 / 64
    const unsigned short* Ah = g_Ah + (size_t)m0 * K_TOT;

    auto load_chunk = [&](int t, int s) {
        const int k0 = t * 64;
        uint32_t Ab = sb + s * ZSTG;
#pragma unroll
        for (int j = 0; j < 2; j++) {               // A tile: 64 rows * 8 chunks
            int idx = tid + j * 256;
            int row = idx >> 3, c = idx & 7;
            cp16(Ab + tswz(row, c * 16), Ah + (size_t)row * K_TOT + k0 + c * 8);
        }
#pragma unroll
        for (int j = 0; j < 4; j++) {               // B tile: 128 rows * 8 chunks
            int idx = tid + j * 256;
            int row = idx >> 3, c = idx & 7;
            cp16(Ab + 8192 + tswz(row, c * 16),
                 g_Ach + (size_t)row * D_DIM + k0 + c * 8);
        }
    };

    load_chunk(0, 0); CP_COMMIT();
    load_chunk(1, 1); CP_COMMIT();

    for (int t = 0; t < NT; t++) {
        CP_WAIT1();
        __syncthreads();
        if (t + 2 < NT) load_chunk(t + 2, (t + 2) % 3);
        CP_COMMIT();
        const int s = t % 3;
        uint32_t Ab = sb + s * ZSTG;
#pragma unroll
        for (int kb = 0; kb < 4; kb++) {
            uint32_t ah[2][4], bh[2][4];
            int colb = kb * 32 + (lane >> 4) * 16;
#pragma unroll
            for (int mt = 0; mt < 2; mt++)
                ldm_x4(ah[mt], Ab + tswz(wm * 32 + mt * 16 + (lane & 15), colb));
#pragma unroll
            for (int nt = 0; nt < 2; nt++)
                ldm_x4(bh[nt], Ab + 8192 + tswz(wn * 32 + nt * 16 + (lane & 15), colb));
#pragma unroll
            for (int mt = 0; mt < 2; mt++)
#pragma unroll
                for (int ns = 0; ns < 4; ns++)
                    mma_fp16(acc[mt][ns], ah[mt],
                             bh[ns >> 1][ns & 1], bh[ns >> 1][2 + (ns & 1)]);
        }
        __syncthreads();
    }

    // epilogue: scale by router weight, store fp16 into cols [2048,2176)
#pragma unroll
    for (int mt = 0; mt < 2; mt++)
#pragma unroll
        for (int ns = 0; ns < 4; ns++) {
            int m = m0 + wm * 32 + mt * 16 + (lane >> 2);
            int n = wn * 32 + ns * 8 + (lane & 3) * 2;
            int e = n >> 4;
            float w0 = g_rw[(size_t)m * E_NUM + e];
            float w1 = g_rw[(size_t)(m + 8) * E_NUM + e];
            ushort2 h0 = {hp(acc[mt][ns][0] * w0), hp(acc[mt][ns][1] * w0)};
            ushort2 h1 = {hp(acc[mt][ns][2] * w1), hp(acc[mt][ns][3] * w1)};
            *reinterpret_cast<ushort2*>(g_Ah + (size_t)m * K_TOT + D_DIM + n) = h0;
            *reinterpret_cast<ushort2*>(g_Ah + (size_t)(m + 8) * K_TOT + D_DIM + n) = h1;
        }
}

// ---------------------------------------------------------------------------
// mgemm (fp16 single-pass, 2 CTAs/SM): out = [X|Z] @ [W|Bcat]^T + bias.
// Tile 64(M) x 128(N), BK=64, 3 stages of 24KB = 72KB -> 2 CTAs/SM (144KB).
// grid 2048 (16 n x 128 m) = 6.92 waves of CTA-pairs.
// 8 warps: wm = warp&1 (2), wn = warp>>1 (4); warp tile 32x32.
// ---------------------------------------------------------------------------
#define MSTG 24576
#define MSMEM (3 * MSTG)

__global__ void __launch_bounds__(256, 2) mgemm_mma_kernel(
    const float* __restrict__ bias, float* __restrict__ out)
{
    extern __shared__ __align__(128) char smem[];
    const uint32_t sb = s2u(smem);
    const int tid = threadIdx.x;
    const int lane = tid & 31, warp = tid >> 5;
    const int wm = warp & 1, wn = warp >> 1;
    const int n0 = blockIdx.x * 128;
    const int m0 = blockIdx.y * 64;

    float acc[2][4][4];
#pragma unroll
    for (int i = 0; i < 2; i++)
#pragma unroll
        for (int j = 0; j < 4; j++)
#pragma unroll
            for (int k = 0; k < 4; k++) acc[i][j][k] = 0.f;

    const int NT = 34;   // 2176 / 64
    const unsigned short* Ah = g_Ah + (size_t)m0 * K_TOT;
    const unsigned short* Bh = g_Bh + (size_t)n0 * K_TOT;

    auto load_chunk = [&](int t, int s) {
        const int k0 = t * 64;
        uint32_t Ab = sb + s * MSTG;
#pragma unroll
        for (int j = 0; j < 2; j++) {               // A tile: 64 rows * 8 chunks
            int idx = tid + j * 256;
            int row = idx >> 3, c = idx & 7;
            cp16(Ab + tswz(row, c * 16), Ah + (size_t)row * K_TOT + k0 + c * 8);
        }
#pragma unroll
        for (int j = 0; j < 4; j++) {               // B tile: 128 rows * 8 chunks
            int idx = tid + j * 256;
            int row = idx >> 3, c = idx & 7;
            cp16(Ab + 8192 + tswz(row, c * 16),
                 Bh + (size_t)row * K_TOT + k0 + c * 8);
        }
    };

    load_chunk(0, 0); CP_COMMIT();
    load_chunk(1, 1); CP_COMMIT();

    for (int t = 0; t < NT; t++) {
        CP_WAIT1();
        __syncthreads();
        if (t + 2 < NT) load_chunk(t + 2, (t + 2) % 3);
        CP_COMMIT();
        const int s = t % 3;
        uint32_t Ab = sb + s * MSTG;
#pragma unroll
        for (int kb = 0; kb < 4; kb++) {
            uint32_t ah[2][4], bh[2][4];
            int colb = kb * 32 + (lane >> 4) * 16;
#pragma unroll
            for (int mt = 0; mt < 2; mt++)
                ldm_x4(ah[mt], Ab + tswz(wm * 32 + mt * 16 + (lane & 15), colb));
#pragma unroll
            for (int nt = 0; nt < 2; nt++)
                ldm_x4(bh[nt], Ab + 8192 + tswz(wn * 32 + nt * 16 + (lane & 15), colb));
#pragma unroll
            for (int mt = 0; mt < 2; mt++)
#pragma unroll
                for (int ns = 0; ns < 4; ns++)
                    mma_fp16(acc[mt][ns], ah[mt],
                             bh[ns >> 1][ns & 1], bh[ns >> 1][2 + (ns & 1)]);
        }
        __syncthreads();
    }

    // epilogue: + bias, direct float2 stores
#pragma unroll
    for (int mt = 0; mt < 2; mt++)
#pragma unroll
        for (int ns = 0; ns < 4; ns++) {
            int m = m0 + wm * 32 + mt * 16 + (lane >> 2);
            int n = n0 + wn * 32 + ns * 8 + (lane & 3) * 2;
            float2 bv = *reinterpret_cast<const float2*>(bias + n);
            float2 v0 = {acc[mt][ns][0] + bv.x, acc[mt][ns][1] + bv.y};
            float2 v1 = {acc[mt][ns][2] + bv.x, acc[mt][ns][3] + bv.y};
            *reinterpret_cast<float2*>(out + (size_t)m * O_DIM + n) = v0;
            *reinterpret_cast<float2*>(out + (size_t)(m + 8) * O_DIM + n) = v1;
        }
}

// ---------------------------------------------------------------------------
extern "C" void kernel_launch(void* const* d_in, const int* in_sizes, int n_in,
                              void* d_out, int out_size)
{
    const float* x    = (const float*)d_in[0];
    const float* W    = (const float*)d_in[1];
    const float* bias = (const float*)d_in[2];
    const float* Wr   = (const float*)d_in[3];
    const float* A    = (const float*)d_in[4];
    const float* Bexp = (const float*)d_in[5];
    float* out = (float*)d_out;

    cudaFuncSetAttribute(prep_rs_kernel,
                         cudaFuncAttributeMaxDynamicSharedMemorySize, 65536);
    cudaFuncSetAttribute(zgemm_mma_kernel,
                         cudaFuncAttributeMaxDynamicSharedMemorySize, ZSMEM);
    cudaFuncSetAttribute(mgemm_mma_kernel,
                         cudaFuncAttributeMaxDynamicSharedMemorySize, MSMEM);

    prep_rs_kernel<<<M_TOT / 32, 256, 65536>>>(x, Wr);
    split_wb_kernel<<<O_DIM, 256>>>(W, Bexp);
    split_acat_kernel<<<KLORA, 256>>>(A);
    zgemm_mma_kernel<<<M_TOT / 64, 256, ZSMEM>>>();
    mgemm_mma_kernel<<<dim3(O_DIM / 128, M_TOT / 64), 256, MSMEM>>>(bias, out);
}